// round 11
// baseline (speedup 1.0000x reference)
#include <cuda_runtime.h>
#include <cuda_fp16.h>
#include <cstdint>

// Problem constants
#define Bsz 16
#define Sl  2048
#define Hd  768
#define NT        (Bsz*(Sl-1))   // 32752 tokens for GEMMs
#define NTOK_FULL (Bsz*Sl)       // 32768

// Scratch (device globals)
__device__ __half g_sequ_h[(size_t)NTOK_FULL*Hd]; // fp16(seqs + E_u[u])
__device__ __half g_ph [(size_t)NT*Hd];           // relu(pairs @ W_hid^T)
__device__ __half g_dc [(size_t)NT*128];          // relu(cat @ W_cd^T)
__device__ __half g_m  [(size_t)NT*Hd];           // relu(cat @ W_cdh^T)

// fp16 weight / embedding copies
__device__ __half g_Ed  [512*128];
__device__ __half g_Ec  [512*128];
__device__ __half g_Wcd [128*256];
__device__ __half g_Whid[768*1536];
__device__ __half g_Wcdh[768*896];

__device__ __forceinline__ float4 ld4(const float* p){
    return *reinterpret_cast<const float4*>(p);
}
__device__ __forceinline__ void cpa16(uint32_t dst, const void* src){
    asm volatile("cp.async.cg.shared.global [%0], [%1], 16;\n" :: "r"(dst), "l"(src));
}
#define LDSM_X4(r0,r1,r2,r3,addr) \
    asm volatile("ldmatrix.sync.aligned.m8n8.x4.shared.b16 {%0,%1,%2,%3}, [%4];" \
        : "=r"(r0),"=r"(r1),"=r"(r2),"=r"(r3) : "r"(addr))

// ---------------------------------------------------------------------------
// Prep: fp16-convert three tensors in one launch
// ---------------------------------------------------------------------------
__global__ void halftri_k(__half* d0, const float* s0, int n0,
                          __half* d1, const float* s1, int n1,
                          __half* d2, const float* s2, int n2){
    int i = (blockIdx.x*blockDim.x + threadIdx.x)*4;
    const float* s; __half* d; int j = i;
    if (j < n0){ s = s0; d = d0; }
    else { j -= n0;
        if (j < n1){ s = s1; d = d1; }
        else { j -= n1; if (j >= n2) return; s = s2; d = d2; }
    }
    float4 v = ld4(s + j);
    __half2* o = reinterpret_cast<__half2*>(d + j);
    o[0] = __floats2half2_rn(v.x, v.y);
    o[1] = __floats2half2_rn(v.z, v.w);
}

// ---------------------------------------------------------------------------
// seqs_u = fp16(seqs + E_u[u])
// ---------------------------------------------------------------------------
__global__ void add_ue_k(const float* __restrict__ seqs,
                         const int*   __restrict__ u,
                         const float* __restrict__ Eu){
    int t = blockIdx.x;
    int uid = __ldg(&u[t]);
    const float4* s4 = reinterpret_cast<const float4*>(seqs + (size_t)t*Hd);
    const float4* e4 = reinterpret_cast<const float4*>(Eu   + (size_t)uid*Hd);
    int i = threadIdx.x;
    float4 a = s4[i], b = e4[i];
    __half2* h2 = reinterpret_cast<__half2*>(g_sequ_h + (size_t)t*Hd + i*4);
    h2[0] = __floats2half2_rn(a.x+b.x, a.y+b.y);
    h2[1] = __floats2half2_rn(a.z+b.z, a.w+b.w);
}

// ---------------------------------------------------------------------------
// FP16 tensor-core GEMM (mma.sync m16n8k16, f32 acc), 3-stage cp.async pipe,
// ldmatrix fragment loads.
// CTA tile 128(M) x 96(N)  -> gemm1/2 grid 2048 CTAs = 6.92 waves (tail ~1%)
// 8 warps in 4(M) x 2(N), warp tile 32x48.
// ONE __syncthreads per k-tile (issue for ti+2 placed after the sync; its
// buffer (ti-1)%3 is read-complete by all warps at that point).
// MODE 0: A = [g_Ed[d[t]] | g_Ec[c[t]]],  K=256,  OUT=128 -> g_dc
// MODE 1: A = g_sequ_h pairs,             K=1536, OUT=768 -> g_ph
// MODE 2: A = [g_ph | g_dc],              K=896,  OUT=768 -> g_m
// ---------------------------------------------------------------------------
#define KTILE 64
#define SSTR  36                        // u32 stride per row
#define A_TILE_B (128*SSTR*4)           // 18432 bytes
#define B_TILE_B (96*SSTR*4)            // 13824 bytes
#define STAGE_B  (A_TILE_B + B_TILE_B)  // 32256 bytes
#define STAGES   3
#define SMEM_TOT (STAGES*STAGE_B)       // 96768 bytes -> 2 CTAs/SM

template<int MODE, int K, int OUT>
__global__ __launch_bounds__(256, 2)
void gemm_f16_k(const int* __restrict__ I0, const int* __restrict__ I1,
                const __half* __restrict__ W){
    extern __shared__ uint32_t smem[];
    const uint32_t sbase = (uint32_t)__cvta_generic_to_shared(smem);

    const int tid  = threadIdx.x;
    const int lane = tid & 31;
    const int warp = tid >> 5;
    const int m0   = blockIdx.y * 128;
    const int n0   = blockIdx.x * 96;
    const int wm   = (warp >> 1) * 32;   // 4 M-warps
    const int wn   = (warp &  1) * 48;   // 2 N-warps
    const int g    = lane >> 2;
    const int c    = lane &  3;

    // ldmatrix per-lane byte offsets (within a stage buffer; B after A)
    uint32_t aoff[2], boff[3];
    {
        int rA = wm + (lane & 7) + ((lane >> 3) & 1)*8;
        int kA = ((lane >> 4) & 1)*4;
        aoff[0] = (uint32_t)((rA     )*SSTR + kA)*4;
        aoff[1] = (uint32_t)((rA + 16)*SSTR + kA)*4;
        int rB = wn + (lane & 7) + ((lane >> 4) & 1)*8;
        int kB = ((lane >> 3) & 1)*4;
        #pragma unroll
        for (int nj = 0; nj < 3; nj++)
            boff[nj] = (uint32_t)(A_TILE_B) + (uint32_t)((rB + nj*16)*SSTR + kB)*4;
    }

    // cp.async geometry: 7 slots x 256 thr = 1792 16B-chunks
    //  slots 0-3: A rows r = (tid>>3) + it*32,      kq = (tid&7)*8
    //  slots 4-6: B rows rb = (tid>>3) + (it-4)*32, kq same
    const int r0 = tid >> 3;
    const int kq = (tid & 7) << 3;

    auto issue_tile = [&](int ch){
        uint32_t aB = sbase + (uint32_t)(ch % STAGES)*STAGE_B;
        uint32_t bB = aB + A_TILE_B;
        const int k0 = ch*KTILE;
        #pragma unroll
        for (int it = 0; it < 4; it++){
            int r = r0 + it*32;
            int t = m0 + r; if (t > NT-1) t = NT-1;
            const __half* sa;
            if (MODE == 0){
                sa = (k0 < 128)
                   ? g_Ed + (size_t)__ldg(&I0[t])*128 + kq + k0
                   : g_Ec + (size_t)__ldg(&I1[t])*128 + kq + (k0 - 128);
            } else if (MODE == 1){
                int row = t + t/2047;   // b*2048 + s from t = b*2047 + s
                sa = g_sequ_h + (size_t)row*Hd + kq + k0;
            } else {
                sa = (k0 < 768)
                   ? g_ph + (size_t)t*768 + kq + k0
                   : g_dc + (size_t)t*128 + kq + (k0 - 768);
            }
            cpa16(aB + (uint32_t)(r*SSTR*4 + kq*2), sa);
        }
        #pragma unroll
        for (int it = 0; it < 3; it++){
            int rb = r0 + it*32;
            int n = n0 + rb; if (n > OUT-1) n = OUT-1;   // clamp (MODE0 2nd blk)
            cpa16(bB + (uint32_t)(rb*SSTR*4 + kq*2),
                  W + (size_t)n*K + kq + k0);
        }
        asm volatile("cp.async.commit_group;\n" ::);
    };

    float acc[2][6][4];
    #pragma unroll
    for (int mi = 0; mi < 2; mi++)
        #pragma unroll
        for (int ni = 0; ni < 6; ni++)
            #pragma unroll
            for (int q = 0; q < 4; q++) acc[mi][ni][q] = 0.f;

    constexpr int NTILES = K / KTILE;
    issue_tile(0);
    issue_tile(1);

    for (int ti = 0; ti < NTILES; ti++){
        // wait for tile ti (1 newer group may stay in flight), single sync
        if (ti + 1 < NTILES) asm volatile("cp.async.wait_group 1;\n" ::);
        else                 asm volatile("cp.async.wait_group 0;\n" ::);
        __syncthreads();
        if (ti + 2 < NTILES) issue_tile(ti + 2);   // writes buf (ti-1)%3: safe

        uint32_t stBase = sbase + (uint32_t)(ti % STAGES)*STAGE_B;

        #pragma unroll
        for (int ks2 = 0; ks2 < 32; ks2 += 8){
            uint32_t afr[2][4], bfr[6][2];
            #pragma unroll
            for (int mi = 0; mi < 2; mi++)
                LDSM_X4(afr[mi][0], afr[mi][1], afr[mi][2], afr[mi][3],
                        stBase + aoff[mi] + ks2*4);
            #pragma unroll
            for (int nj = 0; nj < 3; nj++)
                LDSM_X4(bfr[2*nj][0], bfr[2*nj][1], bfr[2*nj+1][0], bfr[2*nj+1][1],
                        stBase + boff[nj] + ks2*4);
            #pragma unroll
            for (int mi = 0; mi < 2; mi++)
                #pragma unroll
                for (int ni = 0; ni < 6; ni++){
                    asm volatile(
                        "mma.sync.aligned.m16n8k16.row.col.f32.f16.f16.f32 "
                        "{%0,%1,%2,%3}, {%4,%5,%6,%7}, {%8,%9}, {%0,%1,%2,%3};\n"
                        : "+f"(acc[mi][ni][0]), "+f"(acc[mi][ni][1]),
                          "+f"(acc[mi][ni][2]), "+f"(acc[mi][ni][3])
                        : "r"(afr[mi][0]), "r"(afr[mi][1]),
                          "r"(afr[mi][2]), "r"(afr[mi][3]),
                          "r"(bfr[ni][0]), "r"(bfr[ni][1]));
                }
        }
    }

    // Epilogue: ReLU, fp16 store (col guard only matters for MODE0 2nd block)
    __half* Ch = (MODE == 0) ? g_dc : (MODE == 1) ? g_ph : g_m;
    #pragma unroll
    for (int mi = 0; mi < 2; mi++){
        int rbase = m0 + wm + mi*16 + g;
        #pragma unroll
        for (int half = 0; half < 2; half++){
            int t = rbase + half*8;
            if (t < NT){
                #pragma unroll
                for (int ni = 0; ni < 6; ni++){
                    int col = n0 + wn + ni*8 + 2*c;
                    if (MODE != 0 || col < OUT){
                        float x = fmaxf(acc[mi][ni][half*2 + 0], 0.f);
                        float y = fmaxf(acc[mi][ni][half*2 + 1], 0.f);
                        *reinterpret_cast<__half2*>(
                            Ch + (size_t)t*OUT + col) = __floats2half2_rn(x, y);
                    }
                }
            }
        }
    }
}

// ---------------------------------------------------------------------------
// Final: out[b,s] = sequ_h[b,s] + (s<S-1 ? m[b,s] : 0) + (s>=2 ? m[b,s-1] : 0)
// ---------------------------------------------------------------------------
__global__ void final_k(float* __restrict__ out){
    int t = blockIdx.x;
    int s = t & (Sl - 1);
    int b = t >> 11;
    int i = threadIdx.x;

    const __half2* sq = reinterpret_cast<const __half2*>(g_sequ_h + (size_t)t*Hd) + i*2;
    float2 v0 = __half22float2(sq[0]);
    float2 v1 = __half22float2(sq[1]);

    size_t mb = (size_t)b * (Sl - 1);
    if (s < Sl - 1){
        const __half2* mp = reinterpret_cast<const __half2*>(g_m + (mb + s)*Hd) + i*2;
        float2 f0 = __half22float2(mp[0]);
        float2 f1 = __half22float2(mp[1]);
        v0.x += f0.x; v0.y += f0.y; v1.x += f1.x; v1.y += f1.y;
    }
    if (s >= 2){
        const __half2* mp = reinterpret_cast<const __half2*>(g_m + (mb + s - 1)*Hd) + i*2;
        float2 f0 = __half22float2(mp[0]);
        float2 f1 = __half22float2(mp[1]);
        v0.x += f0.x; v0.y += f0.y; v1.x += f1.x; v1.y += f1.y;
    }
    reinterpret_cast<float4*>(out + (size_t)t*Hd)[i] =
        make_float4(v0.x, v0.y, v1.x, v1.y);
}

// ---------------------------------------------------------------------------
extern "C" void kernel_launch(void* const* d_in, const int* in_sizes, int n_in,
                              void* d_out, int out_size){
    const float* seqs  = (const float*)d_in[0];
    const int*   d_idx = (const int*)  d_in[1];
    const int*   c_idx = (const int*)  d_in[2];
    const int*   u_idx = (const int*)  d_in[3];
    const float* E_d   = (const float*)d_in[4];
    const float* E_c   = (const float*)d_in[5];
    const float* E_u   = (const float*)d_in[6];
    const float* W_cd  = (const float*)d_in[7];
    const float* W_hid = (const float*)d_in[8];
    const float* W_cdh = (const float*)d_in[9];
    float* out = (float*)d_out;

    cudaFuncSetAttribute(gemm_f16_k<0,256,128>,  cudaFuncAttributeMaxDynamicSharedMemorySize, SMEM_TOT);
    cudaFuncSetAttribute(gemm_f16_k<1,1536,768>, cudaFuncAttributeMaxDynamicSharedMemorySize, SMEM_TOT);
    cudaFuncSetAttribute(gemm_f16_k<2,896,768>,  cudaFuncAttributeMaxDynamicSharedMemorySize, SMEM_TOT);

    __half *pEd, *pEc, *pWcd, *pWhid, *pWcdh;
    cudaGetSymbolAddress((void**)&pEd,   g_Ed);
    cudaGetSymbolAddress((void**)&pEc,   g_Ec);
    cudaGetSymbolAddress((void**)&pWcd,  g_Wcd);
    cudaGetSymbolAddress((void**)&pWhid, g_Whid);
    cudaGetSymbolAddress((void**)&pWcdh, g_Wcdh);

    // idx 0: convert Ed, Ec, Wcd
    {
        int n0 = 512*128, n1 = 512*128, n2 = 128*256;
        halftri_k<<<((n0+n1+n2)/4 + 255)/256, 256>>>(pEd, E_d, n0, pEc, E_c, n1, pWcd, W_cd, n2);
    }
    // idx 1: convert Whid, Wcdh
    {
        int n0 = 768*1536, n1 = 768*896;
        halftri_k<<<((n0+n1)/4 + 255)/256, 256>>>(pWhid, W_hid, n0, pWcdh, W_cdh, n1,
                                                  nullptr, nullptr, 0);
    }

    // idx 2: seqs_u = fp16(seqs + E_u[u])
    add_ue_k<<<NTOK_FULL, 192>>>(seqs, u_idx, E_u);

    const int MBLK = (NT + 127) / 128;   // 256

    // idx 3 (ncu capture target): ph = relu(pairs @ W_hid^T)  [NT,768]
    gemm_f16_k<1, 1536, 768><<<dim3(8, MBLK), 256, SMEM_TOT>>>(nullptr, nullptr, pWhid);

    // idx 4: d_c = relu(cat(E_d[d], E_c[c]) @ W_cd^T)   [NT,128]
    gemm_f16_k<0, 256, 128><<<dim3(2, MBLK), 256, SMEM_TOT>>>(d_idx, c_idx, pWcd);

    // idx 5: m = relu(cat(ph, d_c) @ W_cdh^T)           [NT,768]
    gemm_f16_k<2, 896, 768><<<dim3(8, MBLK), 256, SMEM_TOT>>>(nullptr, nullptr, pWcdh);

    // idx 6: out = sequ + shifted m adds
    final_k<<<NTOK_FULL, 192>>>(out);
}

// round 12
// speedup vs baseline: 1.0979x; 1.0979x over previous
#include <cuda_runtime.h>
#include <cuda_fp16.h>
#include <cstdint>

// Problem constants
#define Bsz 16
#define Sl  2048
#define Hd  768
#define NT        (Bsz*(Sl-1))   // 32752 tokens for GEMMs
#define NTOK_FULL (Bsz*Sl)       // 32768

// Scratch (device globals)
__device__ __half g_sequ_h[(size_t)NTOK_FULL*Hd]; // fp16(seqs + E_u[u])
__device__ __half g_ph [(size_t)NT*Hd];           // relu(pairs @ W_hid^T)
__device__ __half g_dc [(size_t)NT*128];          // relu(cat @ W_cd^T)
__device__ __half g_m  [(size_t)NT*Hd];           // relu(cat @ W_cdh^T)

// fp16 weight / embedding copies
__device__ __half g_Ed  [512*128];
__device__ __half g_Ec  [512*128];
__device__ __half g_Wcd [128*256];
__device__ __half g_Whid[768*1536];
__device__ __half g_Wcdh[768*896];

__device__ __forceinline__ float4 ld4(const float* p){
    return *reinterpret_cast<const float4*>(p);
}
__device__ __forceinline__ void cpa16(uint32_t dst, const void* src){
    asm volatile("cp.async.cg.shared.global [%0], [%1], 16;\n" :: "r"(dst), "l"(src));
}
#define LDSM_X4(r0,r1,r2,r3,addr) \
    asm volatile("ldmatrix.sync.aligned.m8n8.x4.shared.b16 {%0,%1,%2,%3}, [%4];" \
        : "=r"(r0),"=r"(r1),"=r"(r2),"=r"(r3) : "r"(addr))

// ---------------------------------------------------------------------------
// Prep: fp16-convert three tensors in one launch
// ---------------------------------------------------------------------------
__global__ void halftri_k(__half* d0, const float* s0, int n0,
                          __half* d1, const float* s1, int n1,
                          __half* d2, const float* s2, int n2){
    int i = (blockIdx.x*blockDim.x + threadIdx.x)*4;
    const float* s; __half* d; int j = i;
    if (j < n0){ s = s0; d = d0; }
    else { j -= n0;
        if (j < n1){ s = s1; d = d1; }
        else { j -= n1; if (j >= n2) return; s = s2; d = d2; }
    }
    float4 v = ld4(s + j);
    __half2* o = reinterpret_cast<__half2*>(d + j);
    o[0] = __floats2half2_rn(v.x, v.y);
    o[1] = __floats2half2_rn(v.z, v.w);
}

// ---------------------------------------------------------------------------
// seqs_u = fp16(seqs + E_u[u]); 2 rows/block, 96 thr/row (3 warps), 8 el/thr
// ---------------------------------------------------------------------------
__global__ void add_ue_k(const float* __restrict__ seqs,
                         const int*   __restrict__ u,
                         const float* __restrict__ Eu){
    int half = threadIdx.x / 96;       // row within block
    int j    = threadIdx.x % 96;       // 8-float chunk
    int t = blockIdx.x*2 + half;
    int uid = __ldg(&u[t]);
    const float4* s4 = reinterpret_cast<const float4*>(seqs + (size_t)t*Hd)   + j*2;
    const float4* e4 = reinterpret_cast<const float4*>(Eu   + (size_t)uid*Hd) + j*2;
    float4 a0 = s4[0], a1 = s4[1];
    float4 b0 = e4[0], b1 = e4[1];
    __half2 o[4];
    o[0] = __floats2half2_rn(a0.x+b0.x, a0.y+b0.y);
    o[1] = __floats2half2_rn(a0.z+b0.z, a0.w+b0.w);
    o[2] = __floats2half2_rn(a1.x+b1.x, a1.y+b1.y);
    o[3] = __floats2half2_rn(a1.z+b1.z, a1.w+b1.w);
    *reinterpret_cast<uint4*>(g_sequ_h + (size_t)t*Hd + j*8) =
        *reinterpret_cast<const uint4*>(o);
}

// ---------------------------------------------------------------------------
// FP16 tensor-core GEMM (mma.sync m16n8k16, f32 acc), 3-stage cp.async pipe,
// ldmatrix fragment loads.  (round-9 config: best measured, 126 regs)
//   C[t, n] = relu( sum_k A[t,k] * W[n,k] ), fp16 output
// Block 128x128, KTILE=64 (f16), 256 thr = 8 warps (4x2), warp 32x64.
// MODE 0: A = [g_Ed[d[t]] | g_Ec[c[t]]],  K=256,  OUT=128 -> g_dc
// MODE 1: A = g_sequ_h pairs,             K=1536, OUT=768 -> g_ph
// MODE 2: A = [g_ph | g_dc],              K=896,  OUT=768 -> g_m
// ---------------------------------------------------------------------------
#define KTILE 64
#define SSTR  36                      // u32 stride per row
#define TILE_U32 (128*SSTR)           // 4608 words
#define TILE_B   (TILE_U32*4)         // 18432 bytes
#define STAGES   3
#define SMEM_TOT (STAGES*2*TILE_B)    // 110592 bytes -> 2 CTAs/SM

template<int MODE, int K, int OUT>
__global__ __launch_bounds__(256, 2)
void gemm_f16_k(const int* __restrict__ I0, const int* __restrict__ I1,
                const __half* __restrict__ W){
    extern __shared__ uint32_t smem[];
    const uint32_t sbase = (uint32_t)__cvta_generic_to_shared(smem);

    constexpr int SPLIT = (MODE==0) ? 128 : (MODE==2 ? 768 : (1<<30));

    const int tid  = threadIdx.x;
    const int lane = tid & 31;
    const int warp = tid >> 5;
    const int m0   = blockIdx.y * 128;
    const int n0   = blockIdx.x * 128;
    const int wm   = (warp >> 1) * 32;
    const int wn   = (warp &  1) * 64;
    const int g    = lane >> 2;
    const int c    = lane &  3;

    // ldmatrix per-lane byte offsets (within a tile buffer)
    uint32_t aoff[2], boff[4];
    {
        int rA = wm + (lane & 7) + ((lane >> 3) & 1)*8;
        int kA = ((lane >> 4) & 1)*4;
        aoff[0] = (uint32_t)((rA      )*SSTR + kA)*4;
        aoff[1] = (uint32_t)((rA + 16 )*SSTR + kA)*4;
        int rB = wn + (lane & 7) + ((lane >> 4) & 1)*8;
        int kB = ((lane >> 3) & 1)*4;
        #pragma unroll
        for (int nj = 0; nj < 4; nj++)
            boff[nj] = (uint32_t)((rB + nj*16)*SSTR + kB)*4;
    }

    // Per-thread cp.async load slots: 4 x (16B A-chunk + 16B B-chunk)
    int lr[4], lkq[4];
    const __half* pLo[4]; const __half* pHi[4]; const __half* srcB[4];
    #pragma unroll
    for (int it = 0; it < 4; it++){
        int idx = tid + it*256;
        int r   = idx >> 3;
        int kq  = (idx & 7) << 3;
        lr[it] = r; lkq[it] = kq;
        srcB[it] = W + (size_t)(n0 + r)*K + kq;

        int t = m0 + r; if (t >= NT) t = NT - 1;
        if (MODE == 0){
            pLo[it] = g_Ed + (size_t)__ldg(&I0[t])*128 + kq;
            pHi[it] = g_Ec + (size_t)__ldg(&I1[t])*128 + kq - 128;
        } else if (MODE == 1){
            int row = t + t/2047;     // b*2048 + s from t = b*2047 + s
            pLo[it] = g_sequ_h + (size_t)row*Hd + kq;
            pHi[it] = pLo[it];
        } else {
            pLo[it] = g_ph + (size_t)t*768 + kq;
            pHi[it] = g_dc + (size_t)t*128 + kq - 768;
        }
    }

    auto issue_tile = [&](int ch){
        uint32_t aB = sbase + (uint32_t)(ch % STAGES)*2*TILE_B;
        uint32_t bB = aB + TILE_B;
        int k0 = ch*KTILE;
        #pragma unroll
        for (int it = 0; it < 4; it++){
            uint32_t doff = (uint32_t)(lr[it]*SSTR*4 + lkq[it]*2);
            const __half* sa = ((k0 < SPLIT) ? pLo[it] : pHi[it]) + k0;
            cpa16(aB + doff, sa);
            cpa16(bB + doff, srcB[it] + k0);
        }
        asm volatile("cp.async.commit_group;\n" ::);
    };

    float acc[2][8][4];
    #pragma unroll
    for (int mi = 0; mi < 2; mi++)
        #pragma unroll
        for (int ni = 0; ni < 8; ni++)
            #pragma unroll
            for (int q = 0; q < 4; q++) acc[mi][ni][q] = 0.f;

    constexpr int NTILES = K / KTILE;
    issue_tile(0);
    if (NTILES > 1) issue_tile(1);

    for (int ti = 0; ti < NTILES; ti++){
        if (ti + 2 < NTILES) issue_tile(ti + 2);

        int pend = NTILES - 1 - ti; if (pend > 2) pend = 2;
        if      (pend == 2) asm volatile("cp.async.wait_group 2;\n" ::);
        else if (pend == 1) asm volatile("cp.async.wait_group 1;\n" ::);
        else                asm volatile("cp.async.wait_group 0;\n" ::);
        __syncthreads();

        uint32_t aBase = sbase + (uint32_t)(ti % STAGES)*2*TILE_B;
        uint32_t bBase = aBase + TILE_B;

        #pragma unroll
        for (int ks2 = 0; ks2 < 32; ks2 += 8){
            uint32_t afr[2][4], bfr[8][2];
            #pragma unroll
            for (int mi = 0; mi < 2; mi++)
                LDSM_X4(afr[mi][0], afr[mi][1], afr[mi][2], afr[mi][3],
                        aBase + aoff[mi] + ks2*4);
            #pragma unroll
            for (int nj = 0; nj < 4; nj++)
                LDSM_X4(bfr[2*nj][0], bfr[2*nj][1], bfr[2*nj+1][0], bfr[2*nj+1][1],
                        bBase + boff[nj] + ks2*4);
            #pragma unroll
            for (int mi = 0; mi < 2; mi++)
                #pragma unroll
                for (int ni = 0; ni < 8; ni++){
                    asm volatile(
                        "mma.sync.aligned.m16n8k16.row.col.f32.f16.f16.f32 "
                        "{%0,%1,%2,%3}, {%4,%5,%6,%7}, {%8,%9}, {%0,%1,%2,%3};\n"
                        : "+f"(acc[mi][ni][0]), "+f"(acc[mi][ni][1]),
                          "+f"(acc[mi][ni][2]), "+f"(acc[mi][ni][3])
                        : "r"(afr[mi][0]), "r"(afr[mi][1]),
                          "r"(afr[mi][2]), "r"(afr[mi][3]),
                          "r"(bfr[ni][0]), "r"(bfr[ni][1]));
                }
        }
        __syncthreads();
    }

    // Epilogue: ReLU, fp16 store
    __half* Ch = (MODE == 0) ? g_dc : (MODE == 1) ? g_ph : g_m;
    #pragma unroll
    for (int mi = 0; mi < 2; mi++){
        int rbase = m0 + wm + mi*16 + g;
        #pragma unroll
        for (int half = 0; half < 2; half++){
            int t = rbase + half*8;
            if (t < NT){
                int col = n0 + wn + 2*c;
                #pragma unroll
                for (int ni = 0; ni < 8; ni++){
                    float x = fmaxf(acc[mi][ni][half*2 + 0], 0.f);
                    float y = fmaxf(acc[mi][ni][half*2 + 1], 0.f);
                    *reinterpret_cast<__half2*>(
                        Ch + (size_t)t*OUT + col + ni*8) = __floats2half2_rn(x, y);
                }
            }
        }
    }
}

// ---------------------------------------------------------------------------
// Final: out[b,s] = sequ_h[b,s] + (s<S-1 ? m[b,s] : 0) + (s>=2 ? m[b,s-1] : 0)
// 2 rows/block, 96 thr/row, 8 elements/thread, 16B loads.
// ---------------------------------------------------------------------------
__global__ void final_k(float* __restrict__ out){
    int half = threadIdx.x / 96;
    int j    = threadIdx.x % 96;
    int t = blockIdx.x*2 + half;
    int s = t & (Sl - 1);
    int b = t >> 11;

    uint4 sqv = *reinterpret_cast<const uint4*>(g_sequ_h + (size_t)t*Hd + j*8);
    const __half2* sq = reinterpret_cast<const __half2*>(&sqv);
    float2 v[4];
    #pragma unroll
    for (int q = 0; q < 4; q++) v[q] = __half22float2(sq[q]);

    size_t mb = (size_t)b * (Sl - 1);
    if (s < Sl - 1){
        uint4 mv = *reinterpret_cast<const uint4*>(g_m + (mb + s)*Hd + j*8);
        const __half2* mp = reinterpret_cast<const __half2*>(&mv);
        #pragma unroll
        for (int q = 0; q < 4; q++){
            float2 f = __half22float2(mp[q]);
            v[q].x += f.x; v[q].y += f.y;
        }
    }
    if (s >= 2){
        uint4 mv = *reinterpret_cast<const uint4*>(g_m + (mb + s - 1)*Hd + j*8);
        const __half2* mp = reinterpret_cast<const __half2*>(&mv);
        #pragma unroll
        for (int q = 0; q < 4; q++){
            float2 f = __half22float2(mp[q]);
            v[q].x += f.x; v[q].y += f.y;
        }
    }
    float* op = out + (size_t)t*Hd + j*8;
    *reinterpret_cast<float4*>(op)     = make_float4(v[0].x, v[0].y, v[1].x, v[1].y);
    *reinterpret_cast<float4*>(op + 4) = make_float4(v[2].x, v[2].y, v[3].x, v[3].y);
}

// ---------------------------------------------------------------------------
extern "C" void kernel_launch(void* const* d_in, const int* in_sizes, int n_in,
                              void* d_out, int out_size){
    const float* seqs  = (const float*)d_in[0];
    const int*   d_idx = (const int*)  d_in[1];
    const int*   c_idx = (const int*)  d_in[2];
    const int*   u_idx = (const int*)  d_in[3];
    const float* E_d   = (const float*)d_in[4];
    const float* E_c   = (const float*)d_in[5];
    const float* E_u   = (const float*)d_in[6];
    const float* W_cd  = (const float*)d_in[7];
    const float* W_hid = (const float*)d_in[8];
    const float* W_cdh = (const float*)d_in[9];
    float* out = (float*)d_out;

    cudaFuncSetAttribute(gemm_f16_k<0,256,128>,  cudaFuncAttributeMaxDynamicSharedMemorySize, SMEM_TOT);
    cudaFuncSetAttribute(gemm_f16_k<1,1536,768>, cudaFuncAttributeMaxDynamicSharedMemorySize, SMEM_TOT);
    cudaFuncSetAttribute(gemm_f16_k<2,896,768>,  cudaFuncAttributeMaxDynamicSharedMemorySize, SMEM_TOT);

    __half *pEd, *pEc, *pWcd, *pWhid, *pWcdh;
    cudaGetSymbolAddress((void**)&pEd,   g_Ed);
    cudaGetSymbolAddress((void**)&pEc,   g_Ec);
    cudaGetSymbolAddress((void**)&pWcd,  g_Wcd);
    cudaGetSymbolAddress((void**)&pWhid, g_Whid);
    cudaGetSymbolAddress((void**)&pWcdh, g_Wcdh);

    // idx 0: convert Ed, Ec, Wcd
    {
        int n0 = 512*128, n1 = 512*128, n2 = 128*256;
        halftri_k<<<((n0+n1+n2)/4 + 255)/256, 256>>>(pEd, E_d, n0, pEc, E_c, n1, pWcd, W_cd, n2);
    }
    // idx 1: convert Whid, Wcdh
    {
        int n0 = 768*1536, n1 = 768*896;
        halftri_k<<<((n0+n1)/4 + 255)/256, 256>>>(pWhid, W_hid, n0, pWcdh, W_cdh, n1,
                                                  nullptr, nullptr, 0);
    }

    // idx 2: seqs_u = fp16(seqs + E_u[u])
    add_ue_k<<<NTOK_FULL/2, 192>>>(seqs, u_idx, E_u);

    const int MBLK = (NT + 127) / 128;   // 256

    // idx 3 (ncu capture target): ph = relu(pairs @ W_hid^T)  [NT,768]
    gemm_f16_k<1, 1536, 768><<<dim3(6, MBLK), 256, SMEM_TOT>>>(nullptr, nullptr, pWhid);

    // idx 4: d_c = relu(cat(E_d[d], E_c[c]) @ W_cd^T)   [NT,128]
    gemm_f16_k<0, 256, 128><<<dim3(1, MBLK), 256, SMEM_TOT>>>(d_idx, c_idx, pWcd);

    // idx 5: m = relu(cat(ph, d_c) @ W_cdh^T)           [NT,768]
    gemm_f16_k<2, 896, 768><<<dim3(6, MBLK), 256, SMEM_TOT>>>(nullptr, nullptr, pWcdh);

    // idx 6: out = sequ + shifted m adds
    final_k<<<NTOK_FULL/2, 192>>>(out);
}

// round 13
// speedup vs baseline: 1.1122x; 1.0130x over previous
#include <cuda_runtime.h>
#include <cuda_fp16.h>
#include <cstdint>

// Problem constants
#define Bsz 16
#define Sl  2048
#define Hd  768
#define NT        (Bsz*(Sl-1))   // 32752 tokens for GEMMs
#define NTOK_FULL (Bsz*Sl)       // 32768

// Scratch (device globals)
__device__ __half g_sequ_h[(size_t)NTOK_FULL*Hd]; // fp16(seqs + E_u[u])
__device__ __half g_ph [(size_t)NT*Hd];           // relu(pairs @ W_hid^T)
__device__ __half g_dc [(size_t)NT*128];          // relu(cat @ W_cd^T)
__device__ __half g_m  [(size_t)NT*Hd];           // relu(cat @ W_cdh^T)

// fp16 weight / embedding copies
__device__ __half g_Ed  [512*128];
__device__ __half g_Ec  [512*128];
__device__ __half g_Wcd [128*256];
__device__ __half g_Whid[768*1536];
__device__ __half g_Wcdh[768*896];

__device__ __forceinline__ float4 ld4(const float* p){
    return *reinterpret_cast<const float4*>(p);
}
__device__ __forceinline__ void cpa16(uint32_t dst, const void* src){
    asm volatile("cp.async.cg.shared.global [%0], [%1], 16;\n" :: "r"(dst), "l"(src));
}
#define LDSM_X4(r0,r1,r2,r3,addr) \
    asm volatile("ldmatrix.sync.aligned.m8n8.x4.shared.b16 {%0,%1,%2,%3}, [%4];" \
        : "=r"(r0),"=r"(r1),"=r"(r2),"=r"(r3) : "r"(addr))

// ---------------------------------------------------------------------------
// Prep: fp16-convert three tensors in one launch
// ---------------------------------------------------------------------------
__global__ void halftri_k(__half* d0, const float* s0, int n0,
                          __half* d1, const float* s1, int n1,
                          __half* d2, const float* s2, int n2){
    int i = (blockIdx.x*blockDim.x + threadIdx.x)*4;
    const float* s; __half* d; int j = i;
    if (j < n0){ s = s0; d = d0; }
    else { j -= n0;
        if (j < n1){ s = s1; d = d1; }
        else { j -= n1; if (j >= n2) return; s = s2; d = d2; }
    }
    float4 v = ld4(s + j);
    __half2* o = reinterpret_cast<__half2*>(d + j);
    o[0] = __floats2half2_rn(v.x, v.y);
    o[1] = __floats2half2_rn(v.z, v.w);
}

// ---------------------------------------------------------------------------
// seqs_u = fp16(seqs + E_u[u]); 2 rows/block, 96 thr/row, 8 el/thr
// ---------------------------------------------------------------------------
__global__ void add_ue_k(const float* __restrict__ seqs,
                         const int*   __restrict__ u,
                         const float* __restrict__ Eu){
    int half = threadIdx.x / 96;
    int j    = threadIdx.x % 96;
    int t = blockIdx.x*2 + half;
    int uid = __ldg(&u[t]);
    const float4* s4 = reinterpret_cast<const float4*>(seqs + (size_t)t*Hd)   + j*2;
    const float4* e4 = reinterpret_cast<const float4*>(Eu   + (size_t)uid*Hd) + j*2;
    float4 a0 = s4[0], a1 = s4[1];
    float4 b0 = e4[0], b1 = e4[1];
    __half2 o[4];
    o[0] = __floats2half2_rn(a0.x+b0.x, a0.y+b0.y);
    o[1] = __floats2half2_rn(a0.z+b0.z, a0.w+b0.w);
    o[2] = __floats2half2_rn(a1.x+b1.x, a1.y+b1.y);
    o[3] = __floats2half2_rn(a1.z+b1.z, a1.w+b1.w);
    *reinterpret_cast<uint4*>(g_sequ_h + (size_t)t*Hd + j*8) =
        *reinterpret_cast<const uint4*>(o);
}

// ---------------------------------------------------------------------------
// FP16 tensor-core GEMM (mma.sync m16n8k16, f32 acc), 3-stage cp.async pipe,
// ldmatrix fragment loads with EXPLICIT DOUBLE-BUFFERED FRAGMENTS.
// Address regs minimized (2 LDSM base offsets; cp.async sources recomputed
// per issue) to fund the fragment buffers within the 128-reg/thread cap.
//   C[t, n] = relu( sum_k A[t,k] * W[n,k] ), fp16 output
// Block 128x128, KTILE=64 (f16), 256 thr = 8 warps (4x2), warp 32x64.
// MODE 0: A = [g_Ed[d[t]] | g_Ec[c[t]]],  K=256,  OUT=128 -> g_dc
// MODE 1: A = g_sequ_h pairs,             K=1536, OUT=768 -> g_ph
// MODE 2: A = [g_ph | g_dc],              K=896,  OUT=768 -> g_m
// ---------------------------------------------------------------------------
#define KTILE 64
#define SSTR  36                      // u32 stride per row
#define TILE_U32 (128*SSTR)           // 4608 words
#define TILE_B   (TILE_U32*4)         // 18432 bytes
#define STAGES   3
#define SMEM_TOT (STAGES*2*TILE_B)    // 110592 bytes -> 2 CTAs/SM

template<int MODE, int K, int OUT>
__global__ __launch_bounds__(256, 2)
void gemm_f16_k(const int* __restrict__ I0, const int* __restrict__ I1,
                const __half* __restrict__ W){
    extern __shared__ uint32_t smem[];
    const uint32_t sbase = (uint32_t)__cvta_generic_to_shared(smem);

    const int tid  = threadIdx.x;
    const int lane = tid & 31;
    const int warp = tid >> 5;
    const int m0   = blockIdx.y * 128;
    const int n0   = blockIdx.x * 128;
    const int wm   = (warp >> 1) * 32;
    const int wn   = (warp &  1) * 64;
    const int g    = lane >> 2;
    const int c    = lane &  3;

    // LDSM base byte offsets (mi/nj deltas are compile-time)
    const uint32_t aoff0 = (uint32_t)(((wm + (lane & 7) + ((lane >> 3) & 1)*8)*SSTR
                                      + ((lane >> 4) & 1)*4))*4;
    const uint32_t boff0 = (uint32_t)(((wn + (lane & 7) + ((lane >> 4) & 1)*8)*SSTR
                                      + ((lane >> 3) & 1)*4))*4;

    auto issue_tile = [&](int ch){
        uint32_t aB = sbase + (uint32_t)(ch % STAGES)*2*TILE_B;
        uint32_t bB = aB + TILE_B;
        const int k0 = ch*KTILE;
        #pragma unroll
        for (int it = 0; it < 4; it++){
            int idx = tid + it*256;
            int r   = idx >> 3;
            int kq  = (idx & 7) << 3;
            int t = m0 + r; if (t > NT-1) t = NT-1;
            const __half* sa;
            if (MODE == 0){
                sa = (k0 < 128)
                   ? g_Ed + (size_t)__ldg(&I0[t])*128 + kq + k0
                   : g_Ec + (size_t)__ldg(&I1[t])*128 + kq + (k0 - 128);
            } else if (MODE == 1){
                int row = t + t/2047;   // b*2048 + s from t = b*2047 + s
                sa = g_sequ_h + (size_t)row*Hd + kq + k0;
            } else {
                sa = (k0 < 768)
                   ? g_ph + (size_t)t*768 + kq + k0
                   : g_dc + (size_t)t*128 + kq + (k0 - 768);
            }
            uint32_t doff = (uint32_t)(r*SSTR*4 + kq*2);
            cpa16(aB + doff, sa);
            cpa16(bB + doff, W + (size_t)(n0 + r)*K + kq + k0);
        }
        asm volatile("cp.async.commit_group;\n" ::);
    };

    float acc[2][8][4];
    #pragma unroll
    for (int mi = 0; mi < 2; mi++)
        #pragma unroll
        for (int ni = 0; ni < 8; ni++)
            #pragma unroll
            for (int q = 0; q < 4; q++) acc[mi][ni][q] = 0.f;

    // Double-buffered fragments
    uint32_t afr[2][2][4], bfr[2][8][2];

    constexpr int NTILES = K / KTILE;
    issue_tile(0);
    if (NTILES > 1) issue_tile(1);

    for (int ti = 0; ti < NTILES; ti++){
        if (ti + 2 < NTILES) issue_tile(ti + 2);

        int pend = NTILES - 1 - ti; if (pend > 2) pend = 2;
        if      (pend == 2) asm volatile("cp.async.wait_group 2;\n" ::);
        else if (pend == 1) asm volatile("cp.async.wait_group 1;\n" ::);
        else                asm volatile("cp.async.wait_group 0;\n" ::);
        __syncthreads();

        const uint32_t aBase = sbase + (uint32_t)(ti % STAGES)*2*TILE_B + aoff0;
        const uint32_t bBase = sbase + (uint32_t)(ti % STAGES)*2*TILE_B + TILE_B + boff0;

        // prologue: fragments for k-step 0 into buf 0
        #pragma unroll
        for (int mi = 0; mi < 2; mi++)
            LDSM_X4(afr[0][mi][0], afr[0][mi][1], afr[0][mi][2], afr[0][mi][3],
                    aBase + mi*(16*SSTR*4));
        #pragma unroll
        for (int nj = 0; nj < 4; nj++)
            LDSM_X4(bfr[0][2*nj][0], bfr[0][2*nj][1], bfr[0][2*nj+1][0], bfr[0][2*nj+1][1],
                    bBase + nj*(16*SSTR*4));

        // steps 0..2: prefetch step s+1, multiply step s
        #pragma unroll
        for (int s = 0; s < 3; s++){
            const int nb = (s + 1) & 1;
            const int cb = s & 1;
            #pragma unroll
            for (int mi = 0; mi < 2; mi++)
                LDSM_X4(afr[nb][mi][0], afr[nb][mi][1], afr[nb][mi][2], afr[nb][mi][3],
                        aBase + mi*(16*SSTR*4) + (s+1)*32);
            #pragma unroll
            for (int nj = 0; nj < 4; nj++)
                LDSM_X4(bfr[nb][2*nj][0], bfr[nb][2*nj][1],
                        bfr[nb][2*nj+1][0], bfr[nb][2*nj+1][1],
                        bBase + nj*(16*SSTR*4) + (s+1)*32);
            #pragma unroll
            for (int mi = 0; mi < 2; mi++)
                #pragma unroll
                for (int ni = 0; ni < 8; ni++){
                    asm volatile(
                        "mma.sync.aligned.m16n8k16.row.col.f32.f16.f16.f32 "
                        "{%0,%1,%2,%3}, {%4,%5,%6,%7}, {%8,%9}, {%0,%1,%2,%3};\n"
                        : "+f"(acc[mi][ni][0]), "+f"(acc[mi][ni][1]),
                          "+f"(acc[mi][ni][2]), "+f"(acc[mi][ni][3])
                        : "r"(afr[cb][mi][0]), "r"(afr[cb][mi][1]),
                          "r"(afr[cb][mi][2]), "r"(afr[cb][mi][3]),
                          "r"(bfr[cb][ni][0]), "r"(bfr[cb][ni][1]));
                }
        }
        // final step (buf 1)
        #pragma unroll
        for (int mi = 0; mi < 2; mi++)
            #pragma unroll
            for (int ni = 0; ni < 8; ni++){
                asm volatile(
                    "mma.sync.aligned.m16n8k16.row.col.f32.f16.f16.f32 "
                    "{%0,%1,%2,%3}, {%4,%5,%6,%7}, {%8,%9}, {%0,%1,%2,%3};\n"
                    : "+f"(acc[mi][ni][0]), "+f"(acc[mi][ni][1]),
                      "+f"(acc[mi][ni][2]), "+f"(acc[mi][ni][3])
                    : "r"(afr[1][mi][0]), "r"(afr[1][mi][1]),
                      "r"(afr[1][mi][2]), "r"(afr[1][mi][3]),
                      "r"(bfr[1][ni][0]), "r"(bfr[1][ni][1]));
            }
        __syncthreads();
    }

    // Epilogue: ReLU, fp16 store
    __half* Ch = (MODE == 0) ? g_dc : (MODE == 1) ? g_ph : g_m;
    #pragma unroll
    for (int mi = 0; mi < 2; mi++){
        int rbase = m0 + wm + mi*16 + g;
        #pragma unroll
        for (int half = 0; half < 2; half++){
            int t = rbase + half*8;
            if (t < NT){
                int col = n0 + wn + 2*c;
                #pragma unroll
                for (int ni = 0; ni < 8; ni++){
                    float x = fmaxf(acc[mi][ni][half*2 + 0], 0.f);
                    float y = fmaxf(acc[mi][ni][half*2 + 1], 0.f);
                    *reinterpret_cast<__half2*>(
                        Ch + (size_t)t*OUT + col + ni*8) = __floats2half2_rn(x, y);
                }
            }
        }
    }
}

// ---------------------------------------------------------------------------
// Final: out[b,s] = sequ_h[b,s] + (s<S-1 ? m[b,s] : 0) + (s>=2 ? m[b,s-1] : 0)
// ---------------------------------------------------------------------------
__global__ void final_k(float* __restrict__ out){
    int half = threadIdx.x / 96;
    int j    = threadIdx.x % 96;
    int t = blockIdx.x*2 + half;
    int s = t & (Sl - 1);
    int b = t >> 11;

    uint4 sqv = *reinterpret_cast<const uint4*>(g_sequ_h + (size_t)t*Hd + j*8);
    const __half2* sq = reinterpret_cast<const __half2*>(&sqv);
    float2 v[4];
    #pragma unroll
    for (int q = 0; q < 4; q++) v[q] = __half22float2(sq[q]);

    size_t mb = (size_t)b * (Sl - 1);
    if (s < Sl - 1){
        uint4 mv = *reinterpret_cast<const uint4*>(g_m + (mb + s)*Hd + j*8);
        const __half2* mp = reinterpret_cast<const __half2*>(&mv);
        #pragma unroll
        for (int q = 0; q < 4; q++){
            float2 f = __half22float2(mp[q]);
            v[q].x += f.x; v[q].y += f.y;
        }
    }
    if (s >= 2){
        uint4 mv = *reinterpret_cast<const uint4*>(g_m + (mb + s - 1)*Hd + j*8);
        const __half2* mp = reinterpret_cast<const __half2*>(&mv);
        #pragma unroll
        for (int q = 0; q < 4; q++){
            float2 f = __half22float2(mp[q]);
            v[q].x += f.x; v[q].y += f.y;
        }
    }
    float* op = out + (size_t)t*Hd + j*8;
    *reinterpret_cast<float4*>(op)     = make_float4(v[0].x, v[0].y, v[1].x, v[1].y);
    *reinterpret_cast<float4*>(op + 4) = make_float4(v[2].x, v[2].y, v[3].x, v[3].y);
}

// ---------------------------------------------------------------------------
extern "C" void kernel_launch(void* const* d_in, const int* in_sizes, int n_in,
                              void* d_out, int out_size){
    const float* seqs  = (const float*)d_in[0];
    const int*   d_idx = (const int*)  d_in[1];
    const int*   c_idx = (const int*)  d_in[2];
    const int*   u_idx = (const int*)  d_in[3];
    const float* E_d   = (const float*)d_in[4];
    const float* E_c   = (const float*)d_in[5];
    const float* E_u   = (const float*)d_in[6];
    const float* W_cd  = (const float*)d_in[7];
    const float* W_hid = (const float*)d_in[8];
    const float* W_cdh = (const float*)d_in[9];
    float* out = (float*)d_out;

    cudaFuncSetAttribute(gemm_f16_k<0,256,128>,  cudaFuncAttributeMaxDynamicSharedMemorySize, SMEM_TOT);
    cudaFuncSetAttribute(gemm_f16_k<1,1536,768>, cudaFuncAttributeMaxDynamicSharedMemorySize, SMEM_TOT);
    cudaFuncSetAttribute(gemm_f16_k<2,896,768>,  cudaFuncAttributeMaxDynamicSharedMemorySize, SMEM_TOT);

    __half *pEd, *pEc, *pWcd, *pWhid, *pWcdh;
    cudaGetSymbolAddress((void**)&pEd,   g_Ed);
    cudaGetSymbolAddress((void**)&pEc,   g_Ec);
    cudaGetSymbolAddress((void**)&pWcd,  g_Wcd);
    cudaGetSymbolAddress((void**)&pWhid, g_Whid);
    cudaGetSymbolAddress((void**)&pWcdh, g_Wcdh);

    // idx 0: convert Ed, Ec, Wcd
    {
        int n0 = 512*128, n1 = 512*128, n2 = 128*256;
        halftri_k<<<((n0+n1+n2)/4 + 255)/256, 256>>>(pEd, E_d, n0, pEc, E_c, n1, pWcd, W_cd, n2);
    }
    // idx 1: convert Whid, Wcdh
    {
        int n0 = 768*1536, n1 = 768*896;
        halftri_k<<<((n0+n1)/4 + 255)/256, 256>>>(pWhid, W_hid, n0, pWcdh, W_cdh, n1,
                                                  nullptr, nullptr, 0);
    }

    // idx 2: seqs_u = fp16(seqs + E_u[u])
    add_ue_k<<<NTOK_FULL/2, 192>>>(seqs, u_idx, E_u);

    const int MBLK = (NT + 127) / 128;   // 256

    // idx 3 (ncu capture target): ph = relu(pairs @ W_hid^T)  [NT,768]
    gemm_f16_k<1, 1536, 768><<<dim3(6, MBLK), 256, SMEM_TOT>>>(nullptr, nullptr, pWhid);

    // idx 4: d_c = relu(cat(E_d[d], E_c[c]) @ W_cd^T)   [NT,128]
    gemm_f16_k<0, 256, 128><<<dim3(1, MBLK), 256, SMEM_TOT>>>(d_idx, c_idx, pWcd);

    // idx 5: m = relu(cat(ph, d_c) @ W_cdh^T)           [NT,768]
    gemm_f16_k<2, 896, 768><<<dim3(6, MBLK), 256, SMEM_TOT>>>(nullptr, nullptr, pWcdh);

    // idx 6: out = sequ + shifted m adds
    final_k<<<NTOK_FULL/2, 192>>>(out);
}

// round 14
// speedup vs baseline: 1.1377x; 1.0229x over previous
#include <cuda_runtime.h>
#include <cuda_fp16.h>
#include <cstdint>

// Problem constants
#define Bsz 16
#define Sl  2048
#define Hd  768
#define NT        (Bsz*(Sl-1))   // 32752 tokens for GEMMs
#define NTOK_FULL (Bsz*Sl)       // 32768

// Scratch (device globals)
__device__ __half g_sequ_h[(size_t)NTOK_FULL*Hd]; // fp16(seqs + E_u[u])
__device__ __half g_ph [(size_t)NT*Hd];           // relu(pairs @ W_hid^T)
__device__ __half g_dc [(size_t)NT*128];          // relu(cat @ W_cd^T)
__device__ __half g_m  [(size_t)NT*Hd];           // relu(cat @ W_cdh^T)

// fp16 weight / embedding copies
__device__ __half g_Ed  [512*128];
__device__ __half g_Ec  [512*128];
__device__ __half g_Wcd [128*256];
__device__ __half g_Whid[768*1536];
__device__ __half g_Wcdh[768*896];

__device__ __forceinline__ float4 ld4(const float* p){
    return *reinterpret_cast<const float4*>(p);
}
__device__ __forceinline__ void cpa16(uint32_t dst, const void* src){
    asm volatile("cp.async.cg.shared.global [%0], [%1], 16;\n" :: "r"(dst), "l"(src));
}
#define LDSM_X4(r0,r1,r2,r3,addr) \
    asm volatile("ldmatrix.sync.aligned.m8n8.x4.shared.b16 {%0,%1,%2,%3}, [%4];" \
        : "=r"(r0),"=r"(r1),"=r"(r2),"=r"(r3) : "r"(addr))

// ---------------------------------------------------------------------------
// Prep: fp16-convert three tensors in one launch
// ---------------------------------------------------------------------------
__global__ void halftri_k(__half* d0, const float* s0, int n0,
                          __half* d1, const float* s1, int n1,
                          __half* d2, const float* s2, int n2){
    int i = (blockIdx.x*blockDim.x + threadIdx.x)*4;
    const float* s; __half* d; int j = i;
    if (j < n0){ s = s0; d = d0; }
    else { j -= n0;
        if (j < n1){ s = s1; d = d1; }
        else { j -= n1; if (j >= n2) return; s = s2; d = d2; }
    }
    float4 v = ld4(s + j);
    __half2* o = reinterpret_cast<__half2*>(d + j);
    o[0] = __floats2half2_rn(v.x, v.y);
    o[1] = __floats2half2_rn(v.z, v.w);
}

// ---------------------------------------------------------------------------
// seqs_u = fp16(seqs + E_u[u]); 2 rows/block, 96 thr/row, 8 el/thr
// ---------------------------------------------------------------------------
__global__ void add_ue_k(const float* __restrict__ seqs,
                         const int*   __restrict__ u,
                         const float* __restrict__ Eu){
    int half = threadIdx.x / 96;
    int j    = threadIdx.x % 96;
    int t = blockIdx.x*2 + half;
    int uid = __ldg(&u[t]);
    const float4* s4 = reinterpret_cast<const float4*>(seqs + (size_t)t*Hd)   + j*2;
    const float4* e4 = reinterpret_cast<const float4*>(Eu   + (size_t)uid*Hd) + j*2;
    float4 a0 = s4[0], a1 = s4[1];
    float4 b0 = e4[0], b1 = e4[1];
    __half2 o[4];
    o[0] = __floats2half2_rn(a0.x+b0.x, a0.y+b0.y);
    o[1] = __floats2half2_rn(a0.z+b0.z, a0.w+b0.w);
    o[2] = __floats2half2_rn(a1.x+b1.x, a1.y+b1.y);
    o[3] = __floats2half2_rn(a1.z+b1.z, a1.w+b1.w);
    *reinterpret_cast<uint4*>(g_sequ_h + (size_t)t*Hd + j*8) =
        *reinterpret_cast<const uint4*>(o);
}

// ---------------------------------------------------------------------------
// FP16 tensor-core GEMM (mma.sync m16n8k16, f32 acc), 3-stage cp.async pipe,
// ldmatrix fragment loads with double-buffered fragments (round-13 config,
// measured plateau: tensor=55%, 128 regs, 2 CTA/SM — do not touch).
// MODE 0: A = [g_Ed[d[t]] | g_Ec[c[t]]],  K=256,  OUT=128 -> g_dc
// MODE 1: A = g_sequ_h pairs,             K=1536, OUT=768 -> g_ph
// MODE 2: A = [g_ph | g_dc],              K=896,  OUT=768 -> g_m
// ---------------------------------------------------------------------------
#define KTILE 64
#define SSTR  36                      // u32 stride per row
#define TILE_U32 (128*SSTR)           // 4608 words
#define TILE_B   (TILE_U32*4)         // 18432 bytes
#define STAGES   3
#define SMEM_TOT (STAGES*2*TILE_B)    // 110592 bytes -> 2 CTAs/SM

template<int MODE, int K, int OUT>
__global__ __launch_bounds__(256, 2)
void gemm_f16_k(const int* __restrict__ I0, const int* __restrict__ I1,
                const __half* __restrict__ W){
    extern __shared__ uint32_t smem[];
    const uint32_t sbase = (uint32_t)__cvta_generic_to_shared(smem);

    const int tid  = threadIdx.x;
    const int lane = tid & 31;
    const int warp = tid >> 5;
    const int m0   = blockIdx.y * 128;
    const int n0   = blockIdx.x * 128;
    const int wm   = (warp >> 1) * 32;
    const int wn   = (warp &  1) * 64;
    const int g    = lane >> 2;
    const int c    = lane &  3;

    const uint32_t aoff0 = (uint32_t)(((wm + (lane & 7) + ((lane >> 3) & 1)*8)*SSTR
                                      + ((lane >> 4) & 1)*4))*4;
    const uint32_t boff0 = (uint32_t)(((wn + (lane & 7) + ((lane >> 4) & 1)*8)*SSTR
                                      + ((lane >> 3) & 1)*4))*4;

    auto issue_tile = [&](int ch){
        uint32_t aB = sbase + (uint32_t)(ch % STAGES)*2*TILE_B;
        uint32_t bB = aB + TILE_B;
        const int k0 = ch*KTILE;
        #pragma unroll
        for (int it = 0; it < 4; it++){
            int idx = tid + it*256;
            int r   = idx >> 3;
            int kq  = (idx & 7) << 3;
            int t = m0 + r; if (t > NT-1) t = NT-1;
            const __half* sa;
            if (MODE == 0){
                sa = (k0 < 128)
                   ? g_Ed + (size_t)__ldg(&I0[t])*128 + kq + k0
                   : g_Ec + (size_t)__ldg(&I1[t])*128 + kq + (k0 - 128);
            } else if (MODE == 1){
                int row = t + t/2047;   // b*2048 + s from t = b*2047 + s
                sa = g_sequ_h + (size_t)row*Hd + kq + k0;
            } else {
                sa = (k0 < 768)
                   ? g_ph + (size_t)t*768 + kq + k0
                   : g_dc + (size_t)t*128 + kq + (k0 - 768);
            }
            uint32_t doff = (uint32_t)(r*SSTR*4 + kq*2);
            cpa16(aB + doff, sa);
            cpa16(bB + doff, W + (size_t)(n0 + r)*K + kq + k0);
        }
        asm volatile("cp.async.commit_group;\n" ::);
    };

    float acc[2][8][4];
    #pragma unroll
    for (int mi = 0; mi < 2; mi++)
        #pragma unroll
        for (int ni = 0; ni < 8; ni++)
            #pragma unroll
            for (int q = 0; q < 4; q++) acc[mi][ni][q] = 0.f;

    uint32_t afr[2][2][4], bfr[2][8][2];

    constexpr int NTILES = K / KTILE;
    issue_tile(0);
    if (NTILES > 1) issue_tile(1);

    for (int ti = 0; ti < NTILES; ti++){
        if (ti + 2 < NTILES) issue_tile(ti + 2);

        int pend = NTILES - 1 - ti; if (pend > 2) pend = 2;
        if      (pend == 2) asm volatile("cp.async.wait_group 2;\n" ::);
        else if (pend == 1) asm volatile("cp.async.wait_group 1;\n" ::);
        else                asm volatile("cp.async.wait_group 0;\n" ::);
        __syncthreads();

        const uint32_t aBase = sbase + (uint32_t)(ti % STAGES)*2*TILE_B + aoff0;
        const uint32_t bBase = sbase + (uint32_t)(ti % STAGES)*2*TILE_B + TILE_B + boff0;

        #pragma unroll
        for (int mi = 0; mi < 2; mi++)
            LDSM_X4(afr[0][mi][0], afr[0][mi][1], afr[0][mi][2], afr[0][mi][3],
                    aBase + mi*(16*SSTR*4));
        #pragma unroll
        for (int nj = 0; nj < 4; nj++)
            LDSM_X4(bfr[0][2*nj][0], bfr[0][2*nj][1], bfr[0][2*nj+1][0], bfr[0][2*nj+1][1],
                    bBase + nj*(16*SSTR*4));

        #pragma unroll
        for (int s = 0; s < 3; s++){
            const int nb = (s + 1) & 1;
            const int cb = s & 1;
            #pragma unroll
            for (int mi = 0; mi < 2; mi++)
                LDSM_X4(afr[nb][mi][0], afr[nb][mi][1], afr[nb][mi][2], afr[nb][mi][3],
                        aBase + mi*(16*SSTR*4) + (s+1)*32);
            #pragma unroll
            for (int nj = 0; nj < 4; nj++)
                LDSM_X4(bfr[nb][2*nj][0], bfr[nb][2*nj][1],
                        bfr[nb][2*nj+1][0], bfr[nb][2*nj+1][1],
                        bBase + nj*(16*SSTR*4) + (s+1)*32);
            #pragma unroll
            for (int mi = 0; mi < 2; mi++)
                #pragma unroll
                for (int ni = 0; ni < 8; ni++){
                    asm volatile(
                        "mma.sync.aligned.m16n8k16.row.col.f32.f16.f16.f32 "
                        "{%0,%1,%2,%3}, {%4,%5,%6,%7}, {%8,%9}, {%0,%1,%2,%3};\n"
                        : "+f"(acc[mi][ni][0]), "+f"(acc[mi][ni][1]),
                          "+f"(acc[mi][ni][2]), "+f"(acc[mi][ni][3])
                        : "r"(afr[cb][mi][0]), "r"(afr[cb][mi][1]),
                          "r"(afr[cb][mi][2]), "r"(afr[cb][mi][3]),
                          "r"(bfr[cb][ni][0]), "r"(bfr[cb][ni][1]));
                }
        }
        #pragma unroll
        for (int mi = 0; mi < 2; mi++)
            #pragma unroll
            for (int ni = 0; ni < 8; ni++){
                asm volatile(
                    "mma.sync.aligned.m16n8k16.row.col.f32.f16.f16.f32 "
                    "{%0,%1,%2,%3}, {%4,%5,%6,%7}, {%8,%9}, {%0,%1,%2,%3};\n"
                    : "+f"(acc[mi][ni][0]), "+f"(acc[mi][ni][1]),
                      "+f"(acc[mi][ni][2]), "+f"(acc[mi][ni][3])
                    : "r"(afr[1][mi][0]), "r"(afr[1][mi][1]),
                      "r"(afr[1][mi][2]), "r"(afr[1][mi][3]),
                      "r"(bfr[1][ni][0]), "r"(bfr[1][ni][1]));
            }
        __syncthreads();
    }

    // Epilogue: ReLU, fp16 store
    __half* Ch = (MODE == 0) ? g_dc : (MODE == 1) ? g_ph : g_m;
    #pragma unroll
    for (int mi = 0; mi < 2; mi++){
        int rbase = m0 + wm + mi*16 + g;
        #pragma unroll
        for (int half = 0; half < 2; half++){
            int t = rbase + half*8;
            if (t < NT){
                int col = n0 + wn + 2*c;
                #pragma unroll
                for (int ni = 0; ni < 8; ni++){
                    float x = fmaxf(acc[mi][ni][half*2 + 0], 0.f);
                    float y = fmaxf(acc[mi][ni][half*2 + 1], 0.f);
                    *reinterpret_cast<__half2*>(
                        Ch + (size_t)t*OUT + col + ni*8) = __floats2half2_rn(x, y);
                }
            }
        }
    }
}

// ---------------------------------------------------------------------------
// Final: out[b,s] = sequ_h[b,s] + (s<S-1 ? m[b,s] : 0) + (s>=2 ? m[b,s-1] : 0)
// ---------------------------------------------------------------------------
__global__ void final_k(float* __restrict__ out){
    int half = threadIdx.x / 96;
    int j    = threadIdx.x % 96;
    int t = blockIdx.x*2 + half;
    int s = t & (Sl - 1);
    int b = t >> 11;

    uint4 sqv = *reinterpret_cast<const uint4*>(g_sequ_h + (size_t)t*Hd + j*8);
    const __half2* sq = reinterpret_cast<const __half2*>(&sqv);
    float2 v[4];
    #pragma unroll
    for (int q = 0; q < 4; q++) v[q] = __half22float2(sq[q]);

    size_t mb = (size_t)b * (Sl - 1);
    if (s < Sl - 1){
        uint4 mv = *reinterpret_cast<const uint4*>(g_m + (mb + s)*Hd + j*8);
        const __half2* mp = reinterpret_cast<const __half2*>(&mv);
        #pragma unroll
        for (int q = 0; q < 4; q++){
            float2 f = __half22float2(mp[q]);
            v[q].x += f.x; v[q].y += f.y;
        }
    }
    if (s >= 2){
        uint4 mv = *reinterpret_cast<const uint4*>(g_m + (mb + s - 1)*Hd + j*8);
        const __half2* mp = reinterpret_cast<const __half2*>(&mv);
        #pragma unroll
        for (int q = 0; q < 4; q++){
            float2 f = __half22float2(mp[q]);
            v[q].x += f.x; v[q].y += f.y;
        }
    }
    float* op = out + (size_t)t*Hd + j*8;
    *reinterpret_cast<float4*>(op)     = make_float4(v[0].x, v[0].y, v[1].x, v[1].y);
    *reinterpret_cast<float4*>(op + 4) = make_float4(v[2].x, v[2].y, v[3].x, v[3].y);
}

// ---------------------------------------------------------------------------
// Launch: fork/join multi-stream graph so independent work overlaps.
//   main (legacy) stream: add_ue -> gemm1 -> gemm2 -> final
//   side stream:          prep(all weights) -> gemm0
//   join: gemm2 waits gemm0; side joins main before capture end.
// ---------------------------------------------------------------------------
extern "C" void kernel_launch(void* const* d_in, const int* in_sizes, int n_in,
                              void* d_out, int out_size){
    const float* seqs  = (const float*)d_in[0];
    const int*   d_idx = (const int*)  d_in[1];
    const int*   c_idx = (const int*)  d_in[2];
    const int*   u_idx = (const int*)  d_in[3];
    const float* E_d   = (const float*)d_in[4];
    const float* E_c   = (const float*)d_in[5];
    const float* E_u   = (const float*)d_in[6];
    const float* W_cd  = (const float*)d_in[7];
    const float* W_hid = (const float*)d_in[8];
    const float* W_cdh = (const float*)d_in[9];
    float* out = (float*)d_out;

    static cudaStream_t s1 = nullptr;
    static cudaEvent_t evFork = nullptr, evWhid = nullptr, evG0 = nullptr;
    if (!s1){
        cudaStreamCreateWithFlags(&s1, cudaStreamNonBlocking);
        cudaEventCreateWithFlags(&evFork, cudaEventDisableTiming);
        cudaEventCreateWithFlags(&evWhid, cudaEventDisableTiming);
        cudaEventCreateWithFlags(&evG0,   cudaEventDisableTiming);

        cudaFuncSetAttribute(gemm_f16_k<0,256,128>,  cudaFuncAttributeMaxDynamicSharedMemorySize, SMEM_TOT);
        cudaFuncSetAttribute(gemm_f16_k<1,1536,768>, cudaFuncAttributeMaxDynamicSharedMemorySize, SMEM_TOT);
        cudaFuncSetAttribute(gemm_f16_k<2,896,768>,  cudaFuncAttributeMaxDynamicSharedMemorySize, SMEM_TOT);
    }

    __half *pEd, *pEc, *pWcd, *pWhid, *pWcdh;
    cudaGetSymbolAddress((void**)&pEd,   g_Ed);
    cudaGetSymbolAddress((void**)&pEc,   g_Ec);
    cudaGetSymbolAddress((void**)&pWcd,  g_Wcd);
    cudaGetSymbolAddress((void**)&pWhid, g_Whid);
    cudaGetSymbolAddress((void**)&pWcdh, g_Wcdh);

    const int MBLK = (NT + 127) / 128;   // 256

    // ---- fork
    cudaEventRecord(evFork, 0);
    cudaStreamWaitEvent(s1, evFork, 0);

    // side stream: weight prep, then gemm0
    {
        int n0 = 768*1536, n1 = 768*896, n2 = 128*256;
        halftri_k<<<((n0+n1+n2)/4 + 255)/256, 256, 0, s1>>>(
            pWhid, W_hid, n0, pWcdh, W_cdh, n1, pWcd, W_cd, n2);
    }
    cudaEventRecord(evWhid, s1);    // Whid (+Wcdh,Wcd) ready
    {
        int n0 = 512*128, n1 = 512*128;
        halftri_k<<<((n0+n1)/4 + 255)/256, 256, 0, s1>>>(
            pEd, E_d, n0, pEc, E_c, n1, nullptr, nullptr, 0);
    }
    // gemm0: d_c = relu(cat(E_d[d], E_c[c]) @ W_cd^T)   [NT,128]
    gemm_f16_k<0, 256, 128><<<dim3(1, MBLK), 256, SMEM_TOT, s1>>>(d_idx, c_idx, pWcd);
    cudaEventRecord(evG0, s1);

    // main stream: add_ue (concurrent with prep)
    add_ue_k<<<NTOK_FULL/2, 192>>>(seqs, u_idx, E_u);

    // gemm1 needs Whid + add_ue
    cudaStreamWaitEvent(0, evWhid, 0);
    gemm_f16_k<1, 1536, 768><<<dim3(6, MBLK), 256, SMEM_TOT>>>(nullptr, nullptr, pWhid);

    // gemm2 needs gemm1 (stream order) + gemm0 (event join)
    cudaStreamWaitEvent(0, evG0, 0);
    gemm_f16_k<2, 896, 768><<<dim3(6, MBLK), 256, SMEM_TOT>>>(nullptr, nullptr, pWcdh);

    // final
    final_k<<<NTOK_FULL/2, 192>>>(out);
}